// round 15
// baseline (speedup 1.0000x reference)
#include <cuda_runtime.h>

#define NN 100000
#define NE 1600000
#define NB_SCAN ((NN + 255) / 256)   // 391 scan blocks

typedef unsigned long long ull;

// ---------------- scratch (device globals; no allocation allowed) ----------
__device__ float g_hn[NN * 64];   // h @ W_neigh (transformed features to gather)
__device__ int   g_deg [NN];      // zero at module load; re-zeroed by agg16_k
__device__ int   g_off [NN];      // LOCAL (per-256-chunk) exclusive prefix
__device__ int   g_cur [NN];      // working copy for scatter
__device__ int   g_srcs[NE];      // CSR-by-dst src list
__device__ int   g_bsum[512];     // per-chunk sums
__device__ int   g_bpre[512];     // exclusive prefix of chunk sums

// ---------------- f32x2 packed-FMA helpers ---------------------------------
__device__ __forceinline__ ull pack2(float x) {
    ull r;
    asm("mov.b64 %0, {%1, %1};" : "=l"(r) : "r"(__float_as_uint(x)));
    return r;
}
__device__ __forceinline__ void fma2(ull& d, ull a, ull b) {
    asm("fma.rn.f32x2 %0, %1, %2, %0;" : "+l"(d) : "l"(a), "l"(b));
}
__device__ __forceinline__ float lo2(ull v) { return __uint_as_float((unsigned)v); }
__device__ __forceinline__ float hi2(ull v) { return __uint_as_float((unsigned)(v >> 32)); }

// dtype sniff, per block: int64 ids < 2^31 => all odd 32-bit words are 0.
__device__ __forceinline__ void sniff_block(const int* __restrict__ ei32, int* s_is64) {
    if (threadIdx.x < 32) {
        int v = ei32[2 * threadIdx.x + 1];
        unsigned m = __ballot_sync(0xffffffffu, v != 0);
        if (threadIdx.x == 0) *s_is64 = (m == 0) ? 1 : 0;
    }
}

// ---------------- 1) histogram (g_deg zeroed by previous call's agg16) -----
__global__ void hist_k(const int* __restrict__ ei32) {
    __shared__ int s_is64;
    sniff_block(ei32, &s_is64);
    __syncthreads();
    int e = blockIdx.x * blockDim.x + threadIdx.x;
    if (e < NE) {
        int dst;
        if (s_is64) dst = (int)((const long long*)ei32)[NE + e];
        else        dst = ei32[NE + e];
        atomicAdd(&g_deg[dst], 1);
    }
}

// ---------------- 2) local scan: per-256-chunk exclusive prefix ------------
__global__ void scan1_k() {
    __shared__ int s[256];
    const int tid = threadIdx.x;
    const int i = blockIdx.x * 256 + tid;
    int v = (i < NN) ? g_deg[i] : 0;
    s[tid] = v;
    __syncthreads();
    for (int d = 1; d < 256; d <<= 1) {
        int t = (tid >= d) ? s[tid - d] : 0;
        __syncthreads();
        s[tid] += t;
        __syncthreads();
    }
    if (i < NN) {
        int loc = s[tid] - v;
        g_off[i] = loc;
        g_cur[i] = loc;
    }
    if (tid == 255) g_bsum[blockIdx.x] = s[255];
}

// ---------------- 3) scatter (computes chunk-prefix in-block) --------------
__global__ void scatter_k(const int* __restrict__ ei32) {
    __shared__ int s_is64;
    __shared__ int s_part[256];
    __shared__ int s_bpre[512];
    const int tid = threadIdx.x;

    sniff_block(ei32, &s_is64);

    int a  = (2 * tid     < NB_SCAN) ? g_bsum[2 * tid]     : 0;
    int bq = (2 * tid + 1 < NB_SCAN) ? g_bsum[2 * tid + 1] : 0;
    int tot = a + bq;
    s_part[tid] = tot;
    __syncthreads();
    for (int d = 1; d < 256; d <<= 1) {
        int t = (tid >= d) ? s_part[tid - d] : 0;
        __syncthreads();
        s_part[tid] += t;
        __syncthreads();
    }
    int exc = s_part[tid] - tot;
    s_bpre[2 * tid]     = exc;
    s_bpre[2 * tid + 1] = exc + a;
    __syncthreads();

    if (blockIdx.x == 0) {
        g_bpre[2 * tid]     = s_bpre[2 * tid];
        g_bpre[2 * tid + 1] = s_bpre[2 * tid + 1];
    }

    int e = blockIdx.x * blockDim.x + tid;
    if (e < NE) {
        int src, dst;
        if (s_is64) {
            const long long* p = (const long long*)ei32;
            src = (int)p[e];
            dst = (int)p[NE + e];
        } else {
            src = ei32[e];
            dst = ei32[NE + e];
        }
        int pos = atomicAdd(&g_cur[dst], 1) + s_bpre[dst >> 8];
        g_srcs[pos] = src;
    }
}

// ---------------- dual GEMM (DOUT=64) ---------------------------------------
// 256 threads / block, 64 rows / block. Per thread: 4 rows x 4 cols of BOTH
// matrices (16 ull accs). No swizzle on sh_h (broadcast loads; worst 2-way
// conflict) so unrolled addresses are [base+imm]. k-loop unrolled x4 for MLP.
__global__ void __launch_bounds__(256) gemm64_k(
        const float* __restrict__ hin,
        const float* __restrict__ Ws,
        const float* __restrict__ Wn,
        float* __restrict__ hs_out,
        int relu_in) {
    __shared__ float sh_h [64 * 64];
    __shared__ float sh_ws[64 * 64];
    __shared__ float sh_wn[64 * 64];

    const int tid  = threadIdx.x;
    const int row0 = blockIdx.x * 64;

    {   // weights: 16KB each, float4 loads
        const float4* Ws4 = (const float4*)Ws;
        const float4* Wn4 = (const float4*)Wn;
        float4* sws4 = (float4*)sh_ws;
        float4* swn4 = (float4*)sh_wn;
        for (int i = tid; i < 1024; i += 256) {
            sws4[i] = Ws4[i];
            swn4[i] = Wn4[i];
        }
    }
    for (int i = tid; i < 64 * 64; i += 256) {
        int r = i >> 6, c = i & 63;
        int gr = row0 + r;
        float v = (gr < NN) ? hin[gr * 64 + c] : 0.f;
        if (relu_in) v = fmaxf(v, 0.f);
        sh_h[i] = v;                       // plain row-major, no swizzle
    }
    __syncthreads();

    const int tx = tid & 15;     // 16 column groups x 4 cols (2 pairs)
    const int ty = tid >> 4;     // 16 row groups x 4 rows
    const int r0 = ty * 4;
    const float* hbase = &sh_h[r0 * 64];

    ull accs[4][2], accn[4][2];
#pragma unroll
    for (int r = 0; r < 4; r++)
#pragma unroll
        for (int j = 0; j < 2; j++) { accs[r][j] = 0ull; accn[r][j] = 0ull; }

#pragma unroll 4
    for (int k = 0; k < 64; k++) {
        ulonglong2 wsv = *(const ulonglong2*)&sh_ws[k * 64 + tx * 4];
        ulonglong2 wnv = *(const ulonglong2*)&sh_wn[k * 64 + tx * 4];
        ull hp[4];
#pragma unroll
        for (int r = 0; r < 4; r++)
            hp[r] = pack2(hbase[r * 64 + k]);
#pragma unroll
        for (int r = 0; r < 4; r++) {
            fma2(accs[r][0], hp[r], wsv.x);
            fma2(accs[r][1], hp[r], wsv.y);
            fma2(accn[r][0], hp[r], wnv.x);
            fma2(accn[r][1], hp[r], wnv.y);
        }
    }

#pragma unroll
    for (int r = 0; r < 4; r++) {
        int gr = row0 + r0 + r;
        if (gr < NN) {
            *(float4*)&hs_out[gr * 64 + tx * 4] =
                make_float4(lo2(accs[r][0]), hi2(accs[r][0]),
                            lo2(accs[r][1]), hi2(accs[r][1]));
            *(float4*)&g_hn[gr * 64 + tx * 4] =
                make_float4(lo2(accn[r][0]), hi2(accn[r][0]),
                            lo2(accn[r][1]), hi2(accn[r][1]));
        }
    }
}

// ---------------- dual GEMM (DOUT=16) --------------------------------------
__global__ void gemm16_k(const float* __restrict__ hin,
                         const float* __restrict__ Ws,
                         const float* __restrict__ Wn,
                         float* __restrict__ hs_out,
                         int relu_in) {
    __shared__ float sh_h[32][65];
    __shared__ float sh_ws[64 * 16];
    __shared__ float sh_wn[64 * 16];

    const int tid  = threadIdx.x;
    const int row0 = blockIdx.x * 32;

    for (int i = tid; i < 64 * 16; i += 128) {
        sh_ws[i] = Ws[i];
        sh_wn[i] = Wn[i];
    }
    for (int i = tid; i < 32 * 64; i += 128) {
        int r = i >> 6, c = i & 63;
        int gr = row0 + r;
        float v = (gr < NN) ? hin[gr * 64 + c] : 0.f;
        if (relu_in) v = fmaxf(v, 0.f);
        sh_h[r][c] = v;
    }
    __syncthreads();

    const int tx = tid & 7;      // 8 column groups x 1 pair
    const int ty = tid >> 3;     // 16 row groups x 2 rows
    const int r0 = ty * 2;

    ull accs[2], accn[2];
#pragma unroll
    for (int r = 0; r < 2; r++) { accs[r] = 0ull; accn[r] = 0ull; }

#pragma unroll 4
    for (int k = 0; k < 64; k++) {
        ull ws = *(const ull*)&sh_ws[k * 16 + tx * 2];
        ull wn = *(const ull*)&sh_wn[k * 16 + tx * 2];
        ull h0 = pack2(sh_h[r0][k]);
        ull h1 = pack2(sh_h[r0 + 1][k]);
        fma2(accs[0], h0, ws);
        fma2(accs[1], h1, ws);
        fma2(accn[0], h0, wn);
        fma2(accn[1], h1, wn);
    }

#pragma unroll
    for (int r = 0; r < 2; r++) {
        int gr = row0 + r0 + r;
        if (gr < NN) {
            hs_out[gr * 16 + tx * 2]     = lo2(accs[r]);
            hs_out[gr * 16 + tx * 2 + 1] = hi2(accs[r]);
            g_hn [gr * 16 + tx * 2]      = lo2(accn[r]);
            g_hn [gr * 16 + tx * 2 + 1]  = hi2(accn[r]);
        }
    }
}

// ---------------- fused aggregation + epilogue (RMW into out) --------------
// One warp per dst; 8 edges per iteration (4 independent load chains).
__global__ void agg64_k(const float* __restrict__ b,
                        float* __restrict__ outp) {
    const int gw   = (blockIdx.x * blockDim.x + threadIdx.x) >> 5;
    const int lane = threadIdx.x & 31;
    if (gw >= NN) return;
    const int beg  = g_off[gw] + g_bpre[gw >> 8];
    const int deg  = g_deg[gw];
    const float inv = (deg > 0) ? (1.f / (float)deg) : 1.f;

    const int half = lane >> 4;     // 0 or 1
    const int l4   = lane & 15;     // float4 slot within the 64-float row
    const float4* __restrict__ hn4 = (const float4*)g_hn;

    float a0x = 0.f, a0y = 0.f, a0z = 0.f, a0w = 0.f;
    float a1x = 0.f, a1y = 0.f, a1z = 0.f, a1w = 0.f;
    float a2x = 0.f, a2y = 0.f, a2z = 0.f, a2w = 0.f;
    float a3x = 0.f, a3y = 0.f, a3z = 0.f, a3w = 0.f;
    int i = 0;
    for (; i + 8 <= deg; i += 8) {
        int s0 = g_srcs[beg + i + half];
        int s1 = g_srcs[beg + i + 2 + half];
        int s2 = g_srcs[beg + i + 4 + half];
        int s3 = g_srcs[beg + i + 6 + half];
        float4 v0 = hn4[s0 * 16 + l4];
        float4 v1 = hn4[s1 * 16 + l4];
        float4 v2 = hn4[s2 * 16 + l4];
        float4 v3 = hn4[s3 * 16 + l4];
        a0x += v0.x; a0y += v0.y; a0z += v0.z; a0w += v0.w;
        a1x += v1.x; a1y += v1.y; a1z += v1.z; a1w += v1.w;
        a2x += v2.x; a2y += v2.y; a2z += v2.z; a2w += v2.w;
        a3x += v3.x; a3y += v3.y; a3z += v3.z; a3w += v3.w;
    }
    for (; i + 2 <= deg; i += 2) {
        int s0 = g_srcs[beg + i + half];
        float4 v0 = hn4[s0 * 16 + l4];
        a0x += v0.x; a0y += v0.y; a0z += v0.z; a0w += v0.w;
    }
    if (i < deg && half == 0) {
        int s0 = g_srcs[beg + i];
        float4 v0 = hn4[s0 * 16 + l4];
        a0x += v0.x; a0y += v0.y; a0z += v0.z; a0w += v0.w;
    }
    float ax = (a0x + a1x) + (a2x + a3x);
    float ay = (a0y + a1y) + (a2y + a3y);
    float az = (a0z + a1z) + (a2z + a3z);
    float aw = (a0w + a1w) + (a2w + a3w);
    ax += __shfl_down_sync(0xffffffffu, ax, 16);
    ay += __shfl_down_sync(0xffffffffu, ay, 16);
    az += __shfl_down_sync(0xffffffffu, az, 16);
    aw += __shfl_down_sync(0xffffffffu, aw, 16);

    if (half == 0) {
        float4* op = (float4*)&outp[gw * 64];
        const float4* b4 = (const float4*)b;
        float4 o  = op[l4];
        float4 bb = b4[l4];
        o.x += ax * inv + bb.x;
        o.y += ay * inv + bb.y;
        o.z += az * inv + bb.z;
        o.w += aw * inv + bb.w;
        op[l4] = o;
    }
}

// 16 threads per dst (2 dsts per warp); zeroes g_deg for the next call.
__global__ void agg16_k(const float* __restrict__ b,
                        float* __restrict__ outp) {
    const int t = blockIdx.x * blockDim.x + threadIdx.x;
    const int dst = t >> 4;
    const int l   = t & 15;
    if (dst >= NN) return;
    const int beg = g_off[dst] + g_bpre[dst >> 8];
    const int deg = g_deg[dst];
    const float inv = (deg > 0) ? (1.f / (float)deg) : 1.f;

    float a0 = 0.f, a1 = 0.f;
    int i = 0;
    for (; i + 2 <= deg; i += 2) {
        int s0 = g_srcs[beg + i];
        int s1 = g_srcs[beg + i + 1];
        a0 += g_hn[s0 * 16 + l];
        a1 += g_hn[s1 * 16 + l];
    }
    if (i < deg) a0 += g_hn[g_srcs[beg + i] * 16 + l];
    outp[dst * 16 + l] += (a0 + a1) * inv + b[l];

    if (l == 0) g_deg[dst] = 0;   // leave zeroed for next call's hist
}

// ---------------- launch ---------------------------------------------------
extern "C" void kernel_launch(void* const* d_in, const int* in_sizes, int n_in,
                              void* d_out, int out_size) {
    const float* feat = (const float*)d_in[0];
    const int*   ei32 = (const int*)d_in[1];     // int32 OR int64 (sniffed)
    const float* Ws0 = (const float*)d_in[2];
    const float* Wn0 = (const float*)d_in[3];
    const float* b0  = (const float*)d_in[4];
    const float* Ws1 = (const float*)d_in[5];
    const float* Wn1 = (const float*)d_in[6];
    const float* b1  = (const float*)d_in[7];
    const float* Ws2 = (const float*)d_in[8];
    const float* Wn2 = (const float*)d_in[9];
    const float* b2  = (const float*)d_in[10];

    float* out    = (float*)d_out;
    float* out_h  = out;                          // [NN,16] final logits
    float* out_e0 = out + NN * 16;                // [NN,64] embed0 (pre-relu L0)
    float* out_e1 = out + NN * 16 + NN * 64;      // [NN,64] embed1 (pre-relu L1)

    const int TB = 256;
    const int GEMM64_BLOCKS = (NN + 63) / 64;             // 1563
    const int GEMM16_BLOCKS = (NN + 31) / 32;             // 3125
    const int AGG64_BLOCKS  = (NN * 32 + TB - 1) / TB;    // 1 warp / dst
    const int AGG16_BLOCKS  = (NN * 16 + TB - 1) / TB;    // 16 thr / dst
    const int EDGE_BLOCKS   = (NE + TB - 1) / TB;         // 6250

    // --- CSR build (g_deg pre-zeroed by last call's agg16) ---
    hist_k   <<<EDGE_BLOCKS, TB>>>(ei32);                 // launch 0
    scan1_k  <<<NB_SCAN, 256>>>();                        // launch 1
    scatter_k<<<EDGE_BLOCKS, TB>>>(ei32);                 // launch 2

    // --- layer 0: feat -> embed0 (pre-relu) ---
    gemm64_k<<<GEMM64_BLOCKS, 256>>>(feat, Ws0, Wn0, out_e0, 0);  // launch 3 (profiled)
    agg64_k <<<AGG64_BLOCKS, TB>>>(b0, out_e0);

    // --- layer 1: relu(embed0) -> embed1 (pre-relu) ---
    gemm64_k<<<GEMM64_BLOCKS, 256>>>(out_e0, Ws1, Wn1, out_e1, 1);
    agg64_k <<<AGG64_BLOCKS, TB>>>(b1, out_e1);

    // --- layer 2: relu(embed1) -> logits (16 classes, no relu) ---
    gemm16_k<<<GEMM16_BLOCKS, 128>>>(out_e1, Ws2, Wn2, out_h, 1);
    agg16_k <<<AGG16_BLOCKS, TB>>>(b2, out_h);
}

// round 16
// speedup vs baseline: 1.4824x; 1.4824x over previous
#include <cuda_runtime.h>

#define NN 100000
#define NE 1600000
#define NB_SCAN ((NN + 255) / 256)   // 391 scan blocks

typedef unsigned long long ull;

// ---------------- scratch (device globals; no allocation allowed) ----------
__device__ float g_hn[NN * 64];   // h @ W_neigh (transformed features to gather)
__device__ int   g_deg [NN];      // zero at module load; re-zeroed by agg16_k
__device__ int   g_off [NN];      // LOCAL (per-256-chunk) exclusive prefix
__device__ int   g_cur [NN];      // working copy for scatter
__device__ int   g_srcs[NE];      // CSR-by-dst src list
__device__ int   g_bsum[512];     // per-chunk sums
__device__ int   g_bpre[512];     // exclusive prefix of chunk sums

// ---------------- f32x2 packed-FMA helpers ---------------------------------
__device__ __forceinline__ ull pack2(float x) {
    ull r;
    asm("mov.b64 %0, {%1, %1};" : "=l"(r) : "r"(__float_as_uint(x)));
    return r;
}
__device__ __forceinline__ void fma2(ull& d, ull a, ull b) {
    asm("fma.rn.f32x2 %0, %1, %2, %0;" : "+l"(d) : "l"(a), "l"(b));
}
__device__ __forceinline__ float lo2(ull v) { return __uint_as_float((unsigned)v); }
__device__ __forceinline__ float hi2(ull v) { return __uint_as_float((unsigned)(v >> 32)); }

// dtype sniff, per block: int64 ids < 2^31 => all odd 32-bit words are 0.
__device__ __forceinline__ void sniff_block(const int* __restrict__ ei32, int* s_is64) {
    if (threadIdx.x < 32) {
        int v = ei32[2 * threadIdx.x + 1];
        unsigned m = __ballot_sync(0xffffffffu, v != 0);
        if (threadIdx.x == 0) *s_is64 = (m == 0) ? 1 : 0;
    }
}

// ---------------- 1) histogram (g_deg zeroed by previous call's agg16) -----
__global__ void hist_k(const int* __restrict__ ei32) {
    __shared__ int s_is64;
    sniff_block(ei32, &s_is64);
    __syncthreads();
    int e = blockIdx.x * blockDim.x + threadIdx.x;
    if (e < NE) {
        int dst;
        if (s_is64) dst = (int)((const long long*)ei32)[NE + e];
        else        dst = ei32[NE + e];
        atomicAdd(&g_deg[dst], 1);
    }
}

// ---------------- 2) local scan: per-256-chunk exclusive prefix ------------
__global__ void scan1_k() {
    __shared__ int s[256];
    const int tid = threadIdx.x;
    const int i = blockIdx.x * 256 + tid;
    int v = (i < NN) ? g_deg[i] : 0;
    s[tid] = v;
    __syncthreads();
    for (int d = 1; d < 256; d <<= 1) {
        int t = (tid >= d) ? s[tid - d] : 0;
        __syncthreads();
        s[tid] += t;
        __syncthreads();
    }
    if (i < NN) {
        int loc = s[tid] - v;
        g_off[i] = loc;
        g_cur[i] = loc;
    }
    if (tid == 255) g_bsum[blockIdx.x] = s[255];
}

// ---------------- 3) scatter (computes chunk-prefix in-block) --------------
__global__ void scatter_k(const int* __restrict__ ei32) {
    __shared__ int s_is64;
    __shared__ int s_part[256];
    __shared__ int s_bpre[512];
    const int tid = threadIdx.x;

    sniff_block(ei32, &s_is64);

    int a  = (2 * tid     < NB_SCAN) ? g_bsum[2 * tid]     : 0;
    int bq = (2 * tid + 1 < NB_SCAN) ? g_bsum[2 * tid + 1] : 0;
    int tot = a + bq;
    s_part[tid] = tot;
    __syncthreads();
    for (int d = 1; d < 256; d <<= 1) {
        int t = (tid >= d) ? s_part[tid - d] : 0;
        __syncthreads();
        s_part[tid] += t;
        __syncthreads();
    }
    int exc = s_part[tid] - tot;
    s_bpre[2 * tid]     = exc;
    s_bpre[2 * tid + 1] = exc + a;
    __syncthreads();

    if (blockIdx.x == 0) {
        g_bpre[2 * tid]     = s_bpre[2 * tid];
        g_bpre[2 * tid + 1] = s_bpre[2 * tid + 1];
    }

    int e = blockIdx.x * blockDim.x + tid;
    if (e < NE) {
        int src, dst;
        if (s_is64) {
            const long long* p = (const long long*)ei32;
            src = (int)p[e];
            dst = (int)p[NE + e];
        } else {
            src = ei32[e];
            dst = ei32[NE + e];
        }
        int pos = atomicAdd(&g_cur[dst], 1) + s_bpre[dst >> 8];
        g_srcs[pos] = src;
    }
}

// ---------------- dual GEMM (DOUT=64), high-occupancy tile ------------------
// 256 threads / block, 64 rows / block. Per thread: 4 rows x 4 cols of BOTH
// matrices (16 ull accs). __launch_bounds__(256,4) pins regs <=64 so 4 blocks
// stay resident (43% occ). XOR-swizzled h. k-loop unrolled x4 for LDS MLP.
__global__ void __launch_bounds__(256, 4) gemm64_k(
        const float* __restrict__ hin,
        const float* __restrict__ Ws,
        const float* __restrict__ Wn,
        float* __restrict__ hs_out,
        int relu_in) {
    __shared__ float sh_h [64 * 64];
    __shared__ float sh_ws[64 * 64];
    __shared__ float sh_wn[64 * 64];

    const int tid  = threadIdx.x;
    const int row0 = blockIdx.x * 64;

    {   // weights: 16KB each, float4 loads
        const float4* Ws4 = (const float4*)Ws;
        const float4* Wn4 = (const float4*)Wn;
        float4* sws4 = (float4*)sh_ws;
        float4* swn4 = (float4*)sh_wn;
        for (int i = tid; i < 1024; i += 256) {
            sws4[i] = Ws4[i];
            swn4[i] = Wn4[i];
        }
    }
    for (int i = tid; i < 64 * 64; i += 256) {
        int r = i >> 6, c = i & 63;
        int gr = row0 + r;
        float v = (gr < NN) ? hin[gr * 64 + c] : 0.f;
        if (relu_in) v = fmaxf(v, 0.f);
        sh_h[r * 64 + (c ^ r)] = v;
    }
    __syncthreads();

    const int tx = tid & 15;     // 16 column groups x 4 cols (2 pairs)
    const int ty = tid >> 4;     // 16 row groups x 4 rows
    const int r0 = ty * 4;

    ull accs[4][2], accn[4][2];
#pragma unroll
    for (int r = 0; r < 4; r++)
#pragma unroll
        for (int j = 0; j < 2; j++) { accs[r][j] = 0ull; accn[r][j] = 0ull; }

#pragma unroll 4
    for (int k = 0; k < 64; k++) {
        ulonglong2 wsv = *(const ulonglong2*)&sh_ws[k * 64 + tx * 4];
        ulonglong2 wnv = *(const ulonglong2*)&sh_wn[k * 64 + tx * 4];
        ull hp[4];
#pragma unroll
        for (int r = 0; r < 4; r++)
            hp[r] = pack2(sh_h[(r0 + r) * 64 + (k ^ (r0 + r))]);
#pragma unroll
        for (int r = 0; r < 4; r++) {
            fma2(accs[r][0], hp[r], wsv.x);
            fma2(accs[r][1], hp[r], wsv.y);
            fma2(accn[r][0], hp[r], wnv.x);
            fma2(accn[r][1], hp[r], wnv.y);
        }
    }

#pragma unroll
    for (int r = 0; r < 4; r++) {
        int gr = row0 + r0 + r;
        if (gr < NN) {
            *(float4*)&hs_out[gr * 64 + tx * 4] =
                make_float4(lo2(accs[r][0]), hi2(accs[r][0]),
                            lo2(accs[r][1]), hi2(accs[r][1]));
            *(float4*)&g_hn[gr * 64 + tx * 4] =
                make_float4(lo2(accn[r][0]), hi2(accn[r][0]),
                            lo2(accn[r][1]), hi2(accn[r][1]));
        }
    }
}

// ---------------- dual GEMM (DOUT=16) --------------------------------------
__global__ void gemm16_k(const float* __restrict__ hin,
                         const float* __restrict__ Ws,
                         const float* __restrict__ Wn,
                         float* __restrict__ hs_out,
                         int relu_in) {
    __shared__ float sh_h[32][65];
    __shared__ float sh_ws[64 * 16];
    __shared__ float sh_wn[64 * 16];

    const int tid  = threadIdx.x;
    const int row0 = blockIdx.x * 32;

    for (int i = tid; i < 64 * 16; i += 128) {
        sh_ws[i] = Ws[i];
        sh_wn[i] = Wn[i];
    }
    for (int i = tid; i < 32 * 64; i += 128) {
        int r = i >> 6, c = i & 63;
        int gr = row0 + r;
        float v = (gr < NN) ? hin[gr * 64 + c] : 0.f;
        if (relu_in) v = fmaxf(v, 0.f);
        sh_h[r][c] = v;
    }
    __syncthreads();

    const int tx = tid & 7;      // 8 column groups x 1 pair
    const int ty = tid >> 3;     // 16 row groups x 2 rows
    const int r0 = ty * 2;

    ull accs[2], accn[2];
#pragma unroll
    for (int r = 0; r < 2; r++) { accs[r] = 0ull; accn[r] = 0ull; }

#pragma unroll 4
    for (int k = 0; k < 64; k++) {
        ull ws = *(const ull*)&sh_ws[k * 16 + tx * 2];
        ull wn = *(const ull*)&sh_wn[k * 16 + tx * 2];
        ull h0 = pack2(sh_h[r0][k]);
        ull h1 = pack2(sh_h[r0 + 1][k]);
        fma2(accs[0], h0, ws);
        fma2(accs[1], h1, ws);
        fma2(accn[0], h0, wn);
        fma2(accn[1], h1, wn);
    }

#pragma unroll
    for (int r = 0; r < 2; r++) {
        int gr = row0 + r0 + r;
        if (gr < NN) {
            hs_out[gr * 16 + tx * 2]     = lo2(accs[r]);
            hs_out[gr * 16 + tx * 2 + 1] = hi2(accs[r]);
            g_hn [gr * 16 + tx * 2]      = lo2(accn[r]);
            g_hn [gr * 16 + tx * 2 + 1]  = hi2(accn[r]);
        }
    }
}

// ---------------- fused aggregation + epilogue (RMW into out) --------------
// One warp per dst; 4 edges per iteration (2 independent load chains).
__global__ void agg64_k(const float* __restrict__ b,
                        float* __restrict__ outp) {
    const int gw   = (blockIdx.x * blockDim.x + threadIdx.x) >> 5;
    const int lane = threadIdx.x & 31;
    if (gw >= NN) return;
    const int beg  = g_off[gw] + g_bpre[gw >> 8];
    const int deg  = g_deg[gw];
    const float inv = (deg > 0) ? (1.f / (float)deg) : 1.f;

    const int half = lane >> 4;     // 0 or 1
    const int l4   = lane & 15;     // float4 slot within the 64-float row
    const float4* __restrict__ hn4 = (const float4*)g_hn;

    float ax = 0.f, ay = 0.f, az = 0.f, aw = 0.f;
    float bx = 0.f, by = 0.f, bz = 0.f, bw = 0.f;
    int i = 0;
    for (; i + 4 <= deg; i += 4) {
        int s0 = g_srcs[beg + i + half];
        int s1 = g_srcs[beg + i + 2 + half];
        float4 v0 = hn4[s0 * 16 + l4];
        float4 v1 = hn4[s1 * 16 + l4];
        ax += v0.x; ay += v0.y; az += v0.z; aw += v0.w;
        bx += v1.x; by += v1.y; bz += v1.z; bw += v1.w;
    }
    for (; i + 2 <= deg; i += 2) {
        int s0 = g_srcs[beg + i + half];
        float4 v0 = hn4[s0 * 16 + l4];
        ax += v0.x; ay += v0.y; az += v0.z; aw += v0.w;
    }
    if (i < deg && half == 0) {
        int s0 = g_srcs[beg + i];
        float4 v0 = hn4[s0 * 16 + l4];
        ax += v0.x; ay += v0.y; az += v0.z; aw += v0.w;
    }
    ax += bx; ay += by; az += bz; aw += bw;
    ax += __shfl_down_sync(0xffffffffu, ax, 16);
    ay += __shfl_down_sync(0xffffffffu, ay, 16);
    az += __shfl_down_sync(0xffffffffu, az, 16);
    aw += __shfl_down_sync(0xffffffffu, aw, 16);

    if (half == 0) {
        float4* op = (float4*)&outp[gw * 64];
        const float4* b4 = (const float4*)b;
        float4 o  = op[l4];
        float4 bb = b4[l4];
        o.x += ax * inv + bb.x;
        o.y += ay * inv + bb.y;
        o.z += az * inv + bb.z;
        o.w += aw * inv + bb.w;
        op[l4] = o;
    }
}

// 16 threads per dst (2 dsts per warp); zeroes g_deg for the next call.
__global__ void agg16_k(const float* __restrict__ b,
                        float* __restrict__ outp) {
    const int t = blockIdx.x * blockDim.x + threadIdx.x;
    const int dst = t >> 4;
    const int l   = t & 15;
    if (dst >= NN) return;
    const int beg = g_off[dst] + g_bpre[dst >> 8];
    const int deg = g_deg[dst];
    const float inv = (deg > 0) ? (1.f / (float)deg) : 1.f;

    float a0 = 0.f, a1 = 0.f;
    int i = 0;
    for (; i + 2 <= deg; i += 2) {
        int s0 = g_srcs[beg + i];
        int s1 = g_srcs[beg + i + 1];
        a0 += g_hn[s0 * 16 + l];
        a1 += g_hn[s1 * 16 + l];
    }
    if (i < deg) a0 += g_hn[g_srcs[beg + i] * 16 + l];
    outp[dst * 16 + l] += (a0 + a1) * inv + b[l];

    if (l == 0) g_deg[dst] = 0;   // leave zeroed for next call's hist
}

// ---------------- launch ---------------------------------------------------
extern "C" void kernel_launch(void* const* d_in, const int* in_sizes, int n_in,
                              void* d_out, int out_size) {
    const float* feat = (const float*)d_in[0];
    const int*   ei32 = (const int*)d_in[1];     // int32 OR int64 (sniffed)
    const float* Ws0 = (const float*)d_in[2];
    const float* Wn0 = (const float*)d_in[3];
    const float* b0  = (const float*)d_in[4];
    const float* Ws1 = (const float*)d_in[5];
    const float* Wn1 = (const float*)d_in[6];
    const float* b1  = (const float*)d_in[7];
    const float* Ws2 = (const float*)d_in[8];
    const float* Wn2 = (const float*)d_in[9];
    const float* b2  = (const float*)d_in[10];

    float* out    = (float*)d_out;
    float* out_h  = out;                          // [NN,16] final logits
    float* out_e0 = out + NN * 16;                // [NN,64] embed0 (pre-relu L0)
    float* out_e1 = out + NN * 16 + NN * 64;      // [NN,64] embed1 (pre-relu L1)

    const int TB = 256;
    const int GEMM64_BLOCKS = (NN + 63) / 64;             // 1563
    const int GEMM16_BLOCKS = (NN + 31) / 32;             // 3125
    const int AGG64_BLOCKS  = (NN * 32 + TB - 1) / TB;    // 1 warp / dst
    const int AGG16_BLOCKS  = (NN * 16 + TB - 1) / TB;    // 16 thr / dst
    const int EDGE_BLOCKS   = (NE + TB - 1) / TB;         // 6250

    // --- CSR build (g_deg pre-zeroed by last call's agg16) ---
    hist_k   <<<EDGE_BLOCKS, TB>>>(ei32);                 // launch 0
    scan1_k  <<<NB_SCAN, 256>>>();                        // launch 1
    scatter_k<<<EDGE_BLOCKS, TB>>>(ei32);                 // launch 2

    // --- layer 0: feat -> embed0 (pre-relu) ---
    gemm64_k<<<GEMM64_BLOCKS, 256>>>(feat, Ws0, Wn0, out_e0, 0);  // launch 3 (profiled)
    agg64_k <<<AGG64_BLOCKS, TB>>>(b0, out_e0);

    // --- layer 1: relu(embed0) -> embed1 (pre-relu) ---
    gemm64_k<<<GEMM64_BLOCKS, 256>>>(out_e0, Ws1, Wn1, out_e1, 1);
    agg64_k <<<AGG64_BLOCKS, TB>>>(b1, out_e1);

    // --- layer 2: relu(embed1) -> logits (16 classes, no relu) ---
    gemm16_k<<<GEMM16_BLOCKS, 128>>>(out_e1, Ws2, Wn2, out_h, 1);
    agg16_k <<<AGG16_BLOCKS, TB>>>(b2, out_h);
}

// round 17
// speedup vs baseline: 1.5395x; 1.0385x over previous
#include <cuda_runtime.h>

#define NN 100000
#define NE 1600000
#define NB_SCAN ((NN + 255) / 256)   // 391 scan blocks

typedef unsigned long long ull;

// ---------------- scratch (device globals; no allocation allowed) ----------
__device__ float g_hn[NN * 64];   // h @ W_neigh (transformed features to gather)
__device__ int   g_deg [NN];      // zero at module load; re-zeroed by agg16_k
__device__ int   g_off [NN];      // LOCAL (per-256-chunk) exclusive prefix
__device__ int   g_cur [NN];      // working copy for scatter
__device__ int   g_srcs[NE];      // CSR-by-dst src list
__device__ int   g_bsum[512];     // per-chunk sums
__device__ int   g_bpre[512];     // exclusive prefix of chunk sums

// ---------------- f32x2 packed-FMA helpers ---------------------------------
__device__ __forceinline__ ull pack2(float x) {
    ull r;
    asm("mov.b64 %0, {%1, %1};" : "=l"(r) : "r"(__float_as_uint(x)));
    return r;
}
__device__ __forceinline__ void fma2(ull& d, ull a, ull b) {
    asm("fma.rn.f32x2 %0, %1, %2, %0;" : "+l"(d) : "l"(a), "l"(b));
}
__device__ __forceinline__ float lo2(ull v) { return __uint_as_float((unsigned)v); }
__device__ __forceinline__ float hi2(ull v) { return __uint_as_float((unsigned)(v >> 32)); }

// dtype sniff, per block: int64 ids < 2^31 => all odd 32-bit words are 0.
__device__ __forceinline__ void sniff_block(const int* __restrict__ ei32, int* s_is64) {
    if (threadIdx.x < 32) {
        int v = ei32[2 * threadIdx.x + 1];
        unsigned m = __ballot_sync(0xffffffffu, v != 0);
        if (threadIdx.x == 0) *s_is64 = (m == 0) ? 1 : 0;
    }
}

// ---------------- 1) histogram (g_deg zeroed by previous call's agg16) -----
__global__ void hist_k(const int* __restrict__ ei32) {
    __shared__ int s_is64;
    sniff_block(ei32, &s_is64);
    __syncthreads();
    int e = blockIdx.x * blockDim.x + threadIdx.x;
    if (e < NE) {
        int dst;
        if (s_is64) dst = (int)((const long long*)ei32)[NE + e];
        else        dst = ei32[NE + e];
        atomicAdd(&g_deg[dst], 1);
    }
}

// ---------------- 2) local scan: per-256-chunk exclusive prefix ------------
__global__ void scan1_k() {
    __shared__ int s[256];
    const int tid = threadIdx.x;
    const int i = blockIdx.x * 256 + tid;
    int v = (i < NN) ? g_deg[i] : 0;
    s[tid] = v;
    __syncthreads();
    for (int d = 1; d < 256; d <<= 1) {
        int t = (tid >= d) ? s[tid - d] : 0;
        __syncthreads();
        s[tid] += t;
        __syncthreads();
    }
    if (i < NN) {
        int loc = s[tid] - v;
        g_off[i] = loc;
        g_cur[i] = loc;
    }
    if (tid == 255) g_bsum[blockIdx.x] = s[255];
}

// ---------------- 3) scatter (computes chunk-prefix in-block) --------------
__global__ void scatter_k(const int* __restrict__ ei32) {
    __shared__ int s_is64;
    __shared__ int s_part[256];
    __shared__ int s_bpre[512];
    const int tid = threadIdx.x;

    sniff_block(ei32, &s_is64);

    int a  = (2 * tid     < NB_SCAN) ? g_bsum[2 * tid]     : 0;
    int bq = (2 * tid + 1 < NB_SCAN) ? g_bsum[2 * tid + 1] : 0;
    int tot = a + bq;
    s_part[tid] = tot;
    __syncthreads();
    for (int d = 1; d < 256; d <<= 1) {
        int t = (tid >= d) ? s_part[tid - d] : 0;
        __syncthreads();
        s_part[tid] += t;
        __syncthreads();
    }
    int exc = s_part[tid] - tot;
    s_bpre[2 * tid]     = exc;
    s_bpre[2 * tid + 1] = exc + a;
    __syncthreads();

    if (blockIdx.x == 0) {
        g_bpre[2 * tid]     = s_bpre[2 * tid];
        g_bpre[2 * tid + 1] = s_bpre[2 * tid + 1];
    }

    int e = blockIdx.x * blockDim.x + tid;
    if (e < NE) {
        int src, dst;
        if (s_is64) {
            const long long* p = (const long long*)ei32;
            src = (int)p[e];
            dst = (int)p[NE + e];
        } else {
            src = ei32[e];
            dst = ei32[NE + e];
        }
        int pos = atomicAdd(&g_cur[dst], 1) + s_bpre[dst >> 8];
        g_srcs[pos] = src;
    }
}

// ---------------- dual GEMM (DOUT=64), transposed-h tile --------------------
// 256 threads / block, 64 rows / block, 4 rows x 4 cols of BOTH matrices per
// thread. h stored FEATURE-MAJOR: sh_ht[k*64 + (r ^ ((k&15)<<2))], so the
// 4 rows per thread are ONE LDS.128 (half-warp broadcast -> ~1 wavefront vs 4
// scalar LDS before). Weights 2x LDS.128. LB(256,4) pins regs<=64 (43% occ).
__global__ void __launch_bounds__(256, 4) gemm64_k(
        const float* __restrict__ hin,
        const float* __restrict__ Ws,
        const float* __restrict__ Wn,
        float* __restrict__ hs_out,
        int relu_in) {
    __shared__ float sh_ht[64 * 64];
    __shared__ float sh_ws[64 * 64];
    __shared__ float sh_wn[64 * 64];

    const int tid  = threadIdx.x;
    const int row0 = blockIdx.x * 64;

    {   // weights: 16KB each, float4 loads
        const float4* Ws4 = (const float4*)Ws;
        const float4* Wn4 = (const float4*)Wn;
        float4* sws4 = (float4*)sh_ws;
        float4* swn4 = (float4*)sh_wn;
        for (int i = tid; i < 1024; i += 256) {
            sws4[i] = Ws4[i];
            swn4[i] = Wn4[i];
        }
    }
    // h fill: coalesced global read (consecutive tid -> consecutive k),
    // transposed + 16B-group swizzled store (4-way STS conflict, cheap).
    for (int i = tid; i < 64 * 64; i += 256) {
        int k = i & 63;          // feature index
        int r = i >> 6;          // row within tile
        int gr = row0 + r;
        float v = (gr < NN) ? hin[gr * 64 + k] : 0.f;
        if (relu_in) v = fmaxf(v, 0.f);
        sh_ht[k * 64 + (r ^ ((k & 15) << 2))] = v;
    }
    __syncthreads();

    const int tx = tid & 15;     // 16 column groups x 4 cols (2 pairs)
    const int ty = tid >> 4;     // 16 row groups x 4 rows
    const int r0 = ty * 4;       // 4-aligned; XOR by 4-aligned sw keeps order

    ull accs[4][2], accn[4][2];
#pragma unroll
    for (int r = 0; r < 4; r++)
#pragma unroll
        for (int j = 0; j < 2; j++) { accs[r][j] = 0ull; accn[r][j] = 0ull; }

#pragma unroll 4
    for (int k = 0; k < 64; k++) {
        ulonglong2 wsv = *(const ulonglong2*)&sh_ws[k * 64 + tx * 4];
        ulonglong2 wnv = *(const ulonglong2*)&sh_wn[k * 64 + tx * 4];
        float4 hv = *(const float4*)&sh_ht[k * 64 + (r0 ^ ((k & 15) << 2))];
        ull hp0 = pack2(hv.x);
        ull hp1 = pack2(hv.y);
        ull hp2 = pack2(hv.z);
        ull hp3 = pack2(hv.w);
        fma2(accs[0][0], hp0, wsv.x); fma2(accs[0][1], hp0, wsv.y);
        fma2(accn[0][0], hp0, wnv.x); fma2(accn[0][1], hp0, wnv.y);
        fma2(accs[1][0], hp1, wsv.x); fma2(accs[1][1], hp1, wsv.y);
        fma2(accn[1][0], hp1, wnv.x); fma2(accn[1][1], hp1, wnv.y);
        fma2(accs[2][0], hp2, wsv.x); fma2(accs[2][1], hp2, wsv.y);
        fma2(accn[2][0], hp2, wnv.x); fma2(accn[2][1], hp2, wnv.y);
        fma2(accs[3][0], hp3, wsv.x); fma2(accs[3][1], hp3, wsv.y);
        fma2(accn[3][0], hp3, wnv.x); fma2(accn[3][1], hp3, wnv.y);
    }

#pragma unroll
    for (int r = 0; r < 4; r++) {
        int gr = row0 + r0 + r;
        if (gr < NN) {
            *(float4*)&hs_out[gr * 64 + tx * 4] =
                make_float4(lo2(accs[r][0]), hi2(accs[r][0]),
                            lo2(accs[r][1]), hi2(accs[r][1]));
            *(float4*)&g_hn[gr * 64 + tx * 4] =
                make_float4(lo2(accn[r][0]), hi2(accn[r][0]),
                            lo2(accn[r][1]), hi2(accn[r][1]));
        }
    }
}

// ---------------- dual GEMM (DOUT=16) --------------------------------------
__global__ void gemm16_k(const float* __restrict__ hin,
                         const float* __restrict__ Ws,
                         const float* __restrict__ Wn,
                         float* __restrict__ hs_out,
                         int relu_in) {
    __shared__ float sh_h[32][65];
    __shared__ float sh_ws[64 * 16];
    __shared__ float sh_wn[64 * 16];

    const int tid  = threadIdx.x;
    const int row0 = blockIdx.x * 32;

    for (int i = tid; i < 64 * 16; i += 128) {
        sh_ws[i] = Ws[i];
        sh_wn[i] = Wn[i];
    }
    for (int i = tid; i < 32 * 64; i += 128) {
        int r = i >> 6, c = i & 63;
        int gr = row0 + r;
        float v = (gr < NN) ? hin[gr * 64 + c] : 0.f;
        if (relu_in) v = fmaxf(v, 0.f);
        sh_h[r][c] = v;
    }
    __syncthreads();

    const int tx = tid & 7;      // 8 column groups x 1 pair
    const int ty = tid >> 3;     // 16 row groups x 2 rows
    const int r0 = ty * 2;

    ull accs[2], accn[2];
#pragma unroll
    for (int r = 0; r < 2; r++) { accs[r] = 0ull; accn[r] = 0ull; }

#pragma unroll 4
    for (int k = 0; k < 64; k++) {
        ull ws = *(const ull*)&sh_ws[k * 16 + tx * 2];
        ull wn = *(const ull*)&sh_wn[k * 16 + tx * 2];
        ull h0 = pack2(sh_h[r0][k]);
        ull h1 = pack2(sh_h[r0 + 1][k]);
        fma2(accs[0], h0, ws);
        fma2(accs[1], h1, ws);
        fma2(accn[0], h0, wn);
        fma2(accn[1], h1, wn);
    }

#pragma unroll
    for (int r = 0; r < 2; r++) {
        int gr = row0 + r0 + r;
        if (gr < NN) {
            hs_out[gr * 16 + tx * 2]     = lo2(accs[r]);
            hs_out[gr * 16 + tx * 2 + 1] = hi2(accs[r]);
            g_hn [gr * 16 + tx * 2]      = lo2(accn[r]);
            g_hn [gr * 16 + tx * 2 + 1]  = hi2(accn[r]);
        }
    }
}

// ---------------- fused aggregation + epilogue (RMW into out) --------------
// One warp per dst; 4 edges per iteration (2 independent load chains).
__global__ void agg64_k(const float* __restrict__ b,
                        float* __restrict__ outp) {
    const int gw   = (blockIdx.x * blockDim.x + threadIdx.x) >> 5;
    const int lane = threadIdx.x & 31;
    if (gw >= NN) return;
    const int beg  = g_off[gw] + g_bpre[gw >> 8];
    const int deg  = g_deg[gw];
    const float inv = (deg > 0) ? (1.f / (float)deg) : 1.f;

    const int half = lane >> 4;     // 0 or 1
    const int l4   = lane & 15;     // float4 slot within the 64-float row
    const float4* __restrict__ hn4 = (const float4*)g_hn;

    float ax = 0.f, ay = 0.f, az = 0.f, aw = 0.f;
    float bx = 0.f, by = 0.f, bz = 0.f, bw = 0.f;
    int i = 0;
    for (; i + 4 <= deg; i += 4) {
        int s0 = g_srcs[beg + i + half];
        int s1 = g_srcs[beg + i + 2 + half];
        float4 v0 = hn4[s0 * 16 + l4];
        float4 v1 = hn4[s1 * 16 + l4];
        ax += v0.x; ay += v0.y; az += v0.z; aw += v0.w;
        bx += v1.x; by += v1.y; bz += v1.z; bw += v1.w;
    }
    for (; i + 2 <= deg; i += 2) {
        int s0 = g_srcs[beg + i + half];
        float4 v0 = hn4[s0 * 16 + l4];
        ax += v0.x; ay += v0.y; az += v0.z; aw += v0.w;
    }
    if (i < deg && half == 0) {
        int s0 = g_srcs[beg + i];
        float4 v0 = hn4[s0 * 16 + l4];
        ax += v0.x; ay += v0.y; az += v0.z; aw += v0.w;
    }
    ax += bx; ay += by; az += bz; aw += bw;
    ax += __shfl_down_sync(0xffffffffu, ax, 16);
    ay += __shfl_down_sync(0xffffffffu, ay, 16);
    az += __shfl_down_sync(0xffffffffu, az, 16);
    aw += __shfl_down_sync(0xffffffffu, aw, 16);

    if (half == 0) {
        float4* op = (float4*)&outp[gw * 64];
        const float4* b4 = (const float4*)b;
        float4 o  = op[l4];
        float4 bb = b4[l4];
        o.x += ax * inv + bb.x;
        o.y += ay * inv + bb.y;
        o.z += az * inv + bb.z;
        o.w += aw * inv + bb.w;
        op[l4] = o;
    }
}

// 16 threads per dst (2 dsts per warp); zeroes g_deg for the next call.
__global__ void agg16_k(const float* __restrict__ b,
                        float* __restrict__ outp) {
    const int t = blockIdx.x * blockDim.x + threadIdx.x;
    const int dst = t >> 4;
    const int l   = t & 15;
    if (dst >= NN) return;
    const int beg = g_off[dst] + g_bpre[dst >> 8];
    const int deg = g_deg[dst];
    const float inv = (deg > 0) ? (1.f / (float)deg) : 1.f;

    float a0 = 0.f, a1 = 0.f;
    int i = 0;
    for (; i + 2 <= deg; i += 2) {
        int s0 = g_srcs[beg + i];
        int s1 = g_srcs[beg + i + 1];
        a0 += g_hn[s0 * 16 + l];
        a1 += g_hn[s1 * 16 + l];
    }
    if (i < deg) a0 += g_hn[g_srcs[beg + i] * 16 + l];
    outp[dst * 16 + l] += (a0 + a1) * inv + b[l];

    if (l == 0) g_deg[dst] = 0;   // leave zeroed for next call's hist
}

// ---------------- launch ---------------------------------------------------
extern "C" void kernel_launch(void* const* d_in, const int* in_sizes, int n_in,
                              void* d_out, int out_size) {
    const float* feat = (const float*)d_in[0];
    const int*   ei32 = (const int*)d_in[1];     // int32 OR int64 (sniffed)
    const float* Ws0 = (const float*)d_in[2];
    const float* Wn0 = (const float*)d_in[3];
    const float* b0  = (const float*)d_in[4];
    const float* Ws1 = (const float*)d_in[5];
    const float* Wn1 = (const float*)d_in[6];
    const float* b1  = (const float*)d_in[7];
    const float* Ws2 = (const float*)d_in[8];
    const float* Wn2 = (const float*)d_in[9];
    const float* b2  = (const float*)d_in[10];

    float* out    = (float*)d_out;
    float* out_h  = out;                          // [NN,16] final logits
    float* out_e0 = out + NN * 16;                // [NN,64] embed0 (pre-relu L0)
    float* out_e1 = out + NN * 16 + NN * 64;      // [NN,64] embed1 (pre-relu L1)

    const int TB = 256;
    const int GEMM64_BLOCKS = (NN + 63) / 64;             // 1563
    const int GEMM16_BLOCKS = (NN + 31) / 32;             // 3125
    const int AGG64_BLOCKS  = (NN * 32 + TB - 1) / TB;    // 1 warp / dst
    const int AGG16_BLOCKS  = (NN * 16 + TB - 1) / TB;    // 16 thr / dst
    const int EDGE_BLOCKS   = (NE + TB - 1) / TB;         // 6250

    // --- CSR build (g_deg pre-zeroed by last call's agg16) ---
    hist_k   <<<EDGE_BLOCKS, TB>>>(ei32);                 // launch 0
    scan1_k  <<<NB_SCAN, 256>>>();                        // launch 1
    scatter_k<<<EDGE_BLOCKS, TB>>>(ei32);                 // launch 2

    // --- layer 0: feat -> embed0 (pre-relu) ---
    gemm64_k<<<GEMM64_BLOCKS, 256>>>(feat, Ws0, Wn0, out_e0, 0);  // launch 3 (profiled)
    agg64_k <<<AGG64_BLOCKS, TB>>>(b0, out_e0);

    // --- layer 1: relu(embed0) -> embed1 (pre-relu) ---
    gemm64_k<<<GEMM64_BLOCKS, 256>>>(out_e0, Ws1, Wn1, out_e1, 1);
    agg64_k <<<AGG64_BLOCKS, TB>>>(b1, out_e1);

    // --- layer 2: relu(embed1) -> logits (16 classes, no relu) ---
    gemm16_k<<<GEMM16_BLOCKS, 128>>>(out_e1, Ws2, Wn2, out_h, 1);
    agg16_k <<<AGG16_BLOCKS, TB>>>(b2, out_h);
}